// round 1
// baseline (speedup 1.0000x reference)
#include <cuda_runtime.h>
#include <cuda_bf16.h>
#include <math.h>

// Problem dims
#define BB 1024
#define TT 128
#define EE 300
#define HH 100
#define GG 400     // 4*H
#define VV 50000
#define NB 8       // batches per LSTM CTA

// Scratch (device globals -- no allocation allowed)
__device__ float g_P[VV * GG];        // projected vocab table: emb @ W_ih^T + b  (80 MB)
__device__ float g_out[BB * TT * HH]; // all hidden states (52 MB)
__device__ float g_last[BB * HH];
__device__ float g_label[BB * HH];
__device__ float g_q[BB * 6];         // per_neg @ lin_W^T (pre-cumsum)

// ---------------------------------------------------------------------------
// Kernel 1: P[v,g] = sum_e emb[v,e]*W_ih[g,e] + b_ih[g] + b_hh[g]
// Tiled SGEMM (NT form), 64x64 tile, TK=16, 256 threads, 4x4 per thread.
// ---------------------------------------------------------------------------
__global__ void gemm_P_kernel(const float* __restrict__ emb,
                              const float* __restrict__ W_ih,
                              const float* __restrict__ b_ih,
                              const float* __restrict__ b_hh) {
    __shared__ float As[16][64];
    __shared__ float Bs[16][64];
    const int m0 = blockIdx.x * 64;
    const int n0 = blockIdx.y * 64;
    const int tid = threadIdx.x;
    const int tx = tid & 15;        // 0..15
    const int ty = tid >> 4;        // 0..15

    float acc[4][4];
#pragma unroll
    for (int i = 0; i < 4; i++)
#pragma unroll
        for (int j = 0; j < 4; j++) acc[i][j] = 0.f;

    for (int k0 = 0; k0 < EE; k0 += 16) {
#pragma unroll
        for (int i = 0; i < 4; i++) {
            int idx = tid + i * 256;          // 0..1023
            int m = idx >> 4;                 // 0..63
            int k = idx & 15;
            int gm = m0 + m, gk = k0 + k;
            As[k][m] = (gm < VV && gk < EE) ? emb[gm * EE + gk] : 0.f;
            int gn = n0 + m;
            Bs[k][m] = (gn < GG && gk < EE) ? W_ih[gn * EE + gk] : 0.f;
        }
        __syncthreads();
#pragma unroll
        for (int k = 0; k < 16; k++) {
            float4 a4 = *reinterpret_cast<const float4*>(&As[k][ty * 4]);
            float4 b4 = *reinterpret_cast<const float4*>(&Bs[k][tx * 4]);
            float a[4] = {a4.x, a4.y, a4.z, a4.w};
            float b[4] = {b4.x, b4.y, b4.z, b4.w};
#pragma unroll
            for (int i = 0; i < 4; i++)
#pragma unroll
                for (int j = 0; j < 4; j++) acc[i][j] += a[i] * b[j];
        }
        __syncthreads();
    }

#pragma unroll
    for (int i = 0; i < 4; i++) {
        int gm = m0 + ty * 4 + i;
        if (gm >= VV) continue;
#pragma unroll
        for (int j = 0; j < 4; j++) {
            int gn = n0 + tx * 4 + j;
            if (gn >= GG) continue;
            g_P[gm * GG + gn] = acc[i][j] + b_ih[gn] + b_hh[gn];
        }
    }
}

// ---------------------------------------------------------------------------
// Kernel 2: label_vec[b] = emb[label_word_id[b]] @ ll_W^T + ll_b
// ---------------------------------------------------------------------------
__global__ void label_kernel(const int* __restrict__ label_word_id,
                             const float* __restrict__ emb,
                             const float* __restrict__ ll_W,
                             const float* __restrict__ ll_b) {
    __shared__ float row[EE];
    const int b = blockIdx.x;
    const int w = label_word_id[b];
    for (int e = threadIdx.x; e < EE; e += blockDim.x) row[e] = emb[w * EE + e];
    __syncthreads();
    const int j = threadIdx.x;
    if (j < HH) {
        float s = ll_b[j];
        const float* wr = &ll_W[j * EE];
        for (int e = 0; e < EE; e++) s += row[e] * wr[e];
        g_label[b * HH + j] = s;
    }
}

// ---------------------------------------------------------------------------
// Kernel 3: the LSTM recurrence. 128 CTAs x NB=8 batch rows, 512 threads.
// W_hh kept transposed in shared as Whh_s[k][g] (conflict-free: lanes read
// consecutive g). gates_x comes from g_P gather (L2-resident).
// dyn smem: Whh 40000 + gates 3200 + h 800 + c 800 = 44800 floats = 179200 B
// ---------------------------------------------------------------------------
#define LSTM_SMEM_BYTES (44800 * 4)

__global__ void lstm_kernel(const int* __restrict__ word_id,
                            const int* __restrict__ sen_len,
                            const float* __restrict__ W_hh) {
    extern __shared__ float sm[];
    float* Whh_s   = sm;                     // [100][400]
    float* gates_s = sm + 40000;             // [NB][400]
    float* h_s     = gates_s + NB * GG;      // [NB][100]
    float* c_s     = h_s + NB * HH;          // [NB][100]
    __shared__ int rows_s[NB];
    __shared__ int senl_s[NB];

    const int tid = threadIdx.x;
    const int b0 = blockIdx.x * NB;
    const int g = tid;

    // load W_hh transposed: Whh_s[k*400+g] = W_hh[g*100+k]
    for (int idx = tid; idx < GG * HH; idx += blockDim.x) {
        int k = idx / GG, gg = idx % GG;
        Whh_s[idx] = W_hh[gg * HH + k];
    }
    for (int idx = tid; idx < NB * HH; idx += blockDim.x) {
        h_s[idx] = 0.f;
        c_s[idx] = 0.f;
    }
    if (tid < NB) senl_s[tid] = sen_len[b0 + tid];
    __syncthreads();

    for (int t = 0; t < TT; t++) {
        if (tid < NB) rows_s[tid] = word_id[(b0 + tid) * TT + t];
        __syncthreads();

        if (g < GG) {
            float acc[NB];
#pragma unroll
            for (int nb = 0; nb < NB; nb++) acc[nb] = g_P[rows_s[nb] * GG + g];
#pragma unroll
            for (int k4 = 0; k4 < HH / 4; k4++) {
                float w0 = Whh_s[(4 * k4 + 0) * GG + g];
                float w1 = Whh_s[(4 * k4 + 1) * GG + g];
                float w2 = Whh_s[(4 * k4 + 2) * GG + g];
                float w3 = Whh_s[(4 * k4 + 3) * GG + g];
#pragma unroll
                for (int nb = 0; nb < NB; nb++) {
                    float4 h4 = *reinterpret_cast<const float4*>(&h_s[nb * HH + 4 * k4]);
                    acc[nb] += w0 * h4.x + w1 * h4.y + w2 * h4.z + w3 * h4.w;
                }
            }
#pragma unroll
            for (int nb = 0; nb < NB; nb++) gates_s[nb * GG + g] = acc[nb];
        }
        __syncthreads();

        for (int idx = tid; idx < NB * HH; idx += blockDim.x) {
            int nb = idx / HH, j = idx % HH;
            float gi = gates_s[nb * GG + j];
            float gf = gates_s[nb * GG + HH + j];
            float gg = gates_s[nb * GG + 2 * HH + j];
            float go = gates_s[nb * GG + 3 * HH + j];
            float si = 1.f / (1.f + __expf(-gi));
            float sf = 1.f / (1.f + __expf(-gf));
            float sg = tanhf(gg);
            float so = 1.f / (1.f + __expf(-go));
            float c = sf * c_s[idx] + si * sg;
            float h = so * tanhf(c);
            c_s[idx] = c;
            h_s[idx] = h;
            int b = b0 + nb;
            g_out[(b * TT + t) * HH + j] = h;
            if (t == senl_s[nb] - 1) g_last[b * HH + j] = h;
        }
        __syncthreads();
    }
}

// ---------------------------------------------------------------------------
// Kernel 4: per-batch epilogue: scores, top-4, pos, per_neg, out_f, l_rep, q.
// one CTA (128 threads) per batch element.
// ---------------------------------------------------------------------------
__global__ void catch_kernel(const int* __restrict__ sen_len,
                             const float* __restrict__ lin_W,
                             const float* __restrict__ lin_b,
                             float* __restrict__ dout) {
    __shared__ float label_s[HH];
    __shared__ float last_s[HH];
    __shared__ float scores[TT];
    __shared__ float red_v[TT];
    __shared__ int   red_i[TT];
    __shared__ float topv[4];
    __shared__ int   topi[4];
    __shared__ float pos_s[HH];
    __shared__ float pneg_s[HH];

    const int b = blockIdx.x;
    const int tid = threadIdx.x;
    const int L = sen_len[b];

    if (tid < HH) {
        label_s[tid] = g_label[b * HH + tid];
        last_s[tid]  = g_last[b * HH + tid];
    }
    __syncthreads();

    // scores[t] = out[b,t,:] . label_vec[b]
    {
        float s;
        if (tid < L) {
            s = 0.f;
            const float* o = &g_out[(b * TT + tid) * HH];
            for (int j = 0; j < HH; j++) s += o[j] * label_s[j];
        } else {
            s = -1e30f;
        }
        scores[tid] = s;
    }
    __syncthreads();

    // top-4 (ties -> lower index, matching lax.top_k)
    for (int k = 0; k < 4; k++) {
        red_v[tid] = scores[tid];
        red_i[tid] = tid;
        __syncthreads();
        for (int off = TT / 2; off > 0; off >>= 1) {
            if (tid < off) {
                float v2 = red_v[tid + off];
                int   i2 = red_i[tid + off];
                if (v2 > red_v[tid] || (v2 == red_v[tid] && i2 < red_i[tid])) {
                    red_v[tid] = v2;
                    red_i[tid] = i2;
                }
            }
            __syncthreads();
        }
        if (tid == 0) {
            topv[k] = red_v[0];
            topi[k] = red_i[0];
            scores[red_i[0]] = -1e30f;
        }
        __syncthreads();
    }

    // pos and per_neg
    if (tid < HH) {
        float p = 0.f;
#pragma unroll
        for (int k = 0; k < 4; k++)
            p += g_out[(b * TT + topi[k]) * HH + tid] * topv[k];
        pos_s[tid] = p;

        float s = 0.f;
        int i0 = topi[0], i1 = topi[1], i2 = topi[2], i3 = topi[3];
        for (int t = 0; t < L; t++) {
            if (t == i0 || t == i1 || t == i2 || t == i3) continue;
            s += g_out[(b * TT + t) * HH + tid];
        }
        pneg_s[tid] = s;
    }
    __syncthreads();

    // small linears: out_f, l_rep, q
    if (tid < 6) {
        float bo = lin_b[tid];
        float o = bo, l = bo, q = 0.f;
        const float* w = &lin_W[tid * HH];
        for (int j = 0; j < HH; j++) {
            float wj = w[j];
            o += last_s[j] * wj;
            l += pos_s[j] * wj;
            q += pneg_s[j] * wj;
        }
        dout[b * 6 + tid] = o;                // out_f
        dout[BB * 6 + b * 6 + tid] = l;       // l_rep
        g_q[b * 6 + tid] = q;
    }
}

// ---------------------------------------------------------------------------
// Kernel 5: cumulative sum over batch of q, + lin_b -> r_rep.
// (neg @ lin_W^T = cumsum(per_neg @ lin_W^T) by linearity)
// ---------------------------------------------------------------------------
__global__ void final_kernel(const float* __restrict__ lin_b,
                             float* __restrict__ dout) {
    int r = threadIdx.x;
    if (r < 6) {
        float run = lin_b[r];
        for (int b = 0; b < BB; b++) {
            run += g_q[b * 6 + r];
            dout[2 * BB * 6 + b * 6 + r] = run;   // r_rep
        }
    }
}

// ---------------------------------------------------------------------------
extern "C" void kernel_launch(void* const* d_in, const int* in_sizes, int n_in,
                              void* d_out, int out_size) {
    const int*   word_id       = (const int*)d_in[0];
    const int*   sen_len       = (const int*)d_in[1];
    const int*   label_word_id = (const int*)d_in[2];
    const float* emb           = (const float*)d_in[3];
    const float* W_ih          = (const float*)d_in[4];
    const float* W_hh          = (const float*)d_in[5];
    const float* b_ih          = (const float*)d_in[6];
    const float* b_hh          = (const float*)d_in[7];
    const float* lin_W         = (const float*)d_in[8];
    const float* lin_b         = (const float*)d_in[9];
    const float* ll_W          = (const float*)d_in[10];
    const float* ll_b          = (const float*)d_in[11];
    float* out = (float*)d_out;

    cudaFuncSetAttribute(lstm_kernel,
                         cudaFuncAttributeMaxDynamicSharedMemorySize,
                         LSTM_SMEM_BYTES);

    dim3 ggrid((VV + 63) / 64, (GG + 63) / 64);
    gemm_P_kernel<<<ggrid, 256>>>(emb, W_ih, b_ih, b_hh);
    label_kernel<<<BB, 128>>>(label_word_id, emb, ll_W, ll_b);
    lstm_kernel<<<BB / NB, 512, LSTM_SMEM_BYTES>>>(word_id, sen_len, W_hh);
    catch_kernel<<<BB, 128>>>(sen_len, lin_W, lin_b, out);
    final_kernel<<<1, 32>>>(lin_b, out);
}

// round 2
// speedup vs baseline: 1.5727x; 1.5727x over previous
#include <cuda_runtime.h>
#include <cuda_bf16.h>
#include <math.h>

// Problem dims
#define BB 1024
#define TT 128
#define EE 300
#define HH 100
#define GG 400     // 4*H
#define VV 50000
#define NB 8       // batches per LSTM CTA

typedef unsigned long long ull;

// Scratch (device globals -- no allocation allowed)
__device__ float g_P[VV * GG];        // projected vocab table: emb @ W_ih^T + b  (80 MB)
__device__ float g_out[BB * TT * HH]; // all hidden states (52 MB)
__device__ float g_last[BB * HH];
__device__ float g_label[BB * HH];
__device__ float g_q[BB * 6];         // per_neg @ lin_W^T (pre-cumsum)

// ---------------- PTX helpers ----------------
__device__ __forceinline__ unsigned f2tf32(float x) {
    unsigned u;
    asm("cvt.rna.tf32.f32 %0, %1;" : "=r"(u) : "f"(x));
    return u;
}

__device__ __forceinline__ void mma_tf32(float* d, const unsigned* a, const unsigned* b) {
    asm volatile(
        "mma.sync.aligned.m16n8k8.row.col.f32.tf32.tf32.f32 "
        "{%0,%1,%2,%3}, {%4,%5,%6,%7}, {%8,%9}, {%0,%1,%2,%3};"
        : "+f"(d[0]), "+f"(d[1]), "+f"(d[2]), "+f"(d[3])
        : "r"(a[0]), "r"(a[1]), "r"(a[2]), "r"(a[3]), "r"(b[0]), "r"(b[1]));
}

__device__ __forceinline__ ull pack2(float lo, float hi) {
    ull r;
    asm("mov.b64 %0, {%1, %2};" : "=l"(r) : "r"(__float_as_uint(lo)), "r"(__float_as_uint(hi)));
    return r;
}

__device__ __forceinline__ ull ffma2(ull a, ull b, ull c) {
    ull d;
    asm("fma.rn.f32x2 %0, %1, %2, %3;" : "=l"(d) : "l"(a), "l"(b), "l"(c));
    return d;
}

__device__ __forceinline__ ull add2(ull a, ull b) {
    ull d;
    asm("add.rn.f32x2 %0, %1, %2;" : "=l"(d) : "l"(a), "l"(b));
    return d;
}

__device__ __forceinline__ float fast_tanh(float x) {
    float ax = fabsf(x);
    float e = __expf(-2.f * ax);
    float r = (1.f - e) / (1.f + e);
    return copysignf(r, x);
}

// ---------------------------------------------------------------------------
// Kernel 1: P[v,g] = sum_e emb[v,e]*W_ih[g,e] + b_ih[g] + b_hh[g]
// tf32 tensor-core GEMM. CTA tile 128x64, BK=16, 8 warps (4m x 2n),
// each warp 32x32 (2 m16 x 4 n8 mma tiles).
// ---------------------------------------------------------------------------
#define AS_STRIDE 132
#define BS_STRIDE 68

__global__ void gemm_P_kernel(const float* __restrict__ emb,
                              const float* __restrict__ W_ih,
                              const float* __restrict__ b_ih,
                              const float* __restrict__ b_hh) {
    __shared__ unsigned As[16 * AS_STRIDE];   // [k][m] tf32 bits
    __shared__ unsigned Bs[16 * BS_STRIDE];   // [k][n] tf32 bits

    const int m0 = blockIdx.x * 128;
    const int n0 = blockIdx.y * 64;
    const int tid = threadIdx.x;
    const int lane = tid & 31;
    const int wid = tid >> 5;
    const int warp_m = wid & 3;    // 0..3
    const int warp_n = wid >> 2;   // 0..1

    float acc[2][4][4];
#pragma unroll
    for (int mt = 0; mt < 2; mt++)
#pragma unroll
        for (int nt = 0; nt < 4; nt++)
#pragma unroll
            for (int c = 0; c < 4; c++) acc[mt][nt][c] = 0.f;

    for (int k0 = 0; k0 < EE; k0 += 16) {
        // load A: 128 rows x 16 k = 512 float4, 2 per thread
#pragma unroll
        for (int i = 0; i < 2; i++) {
            int idx = tid + i * 256;
            int q = idx & 3;        // float4 index within 16-k chunk
            int m = idx >> 2;       // 0..127
            int gm = m0 + m;
            int gk = k0 + q * 4;
            float4 v = make_float4(0.f, 0.f, 0.f, 0.f);
            if (gm < VV && gk < EE)
                v = *reinterpret_cast<const float4*>(&emb[gm * EE + gk]);
            As[(q * 4 + 0) * AS_STRIDE + m] = f2tf32(v.x);
            As[(q * 4 + 1) * AS_STRIDE + m] = f2tf32(v.y);
            As[(q * 4 + 2) * AS_STRIDE + m] = f2tf32(v.z);
            As[(q * 4 + 3) * AS_STRIDE + m] = f2tf32(v.w);
        }
        // load B: 64 rows x 16 k = 256 float4, 1 per thread
        {
            int q = tid & 3;
            int n = tid >> 2;       // 0..63
            int gn = n0 + n;
            int gk = k0 + q * 4;
            float4 v = make_float4(0.f, 0.f, 0.f, 0.f);
            if (gn < GG && gk < EE)
                v = *reinterpret_cast<const float4*>(&W_ih[gn * EE + gk]);
            Bs[(q * 4 + 0) * BS_STRIDE + n] = f2tf32(v.x);
            Bs[(q * 4 + 1) * BS_STRIDE + n] = f2tf32(v.y);
            Bs[(q * 4 + 2) * BS_STRIDE + n] = f2tf32(v.z);
            Bs[(q * 4 + 3) * BS_STRIDE + n] = f2tf32(v.w);
        }
        __syncthreads();

#pragma unroll
        for (int kk = 0; kk < 2; kk++) {
            const int ks = kk * 8;
            const int kf = ks + (lane & 3);
            unsigned afr[2][4];
#pragma unroll
            for (int mt = 0; mt < 2; mt++) {
                int m = warp_m * 32 + mt * 16 + (lane >> 2);
                afr[mt][0] = As[kf * AS_STRIDE + m];
                afr[mt][1] = As[kf * AS_STRIDE + m + 8];
                afr[mt][2] = As[(kf + 4) * AS_STRIDE + m];
                afr[mt][3] = As[(kf + 4) * AS_STRIDE + m + 8];
            }
            unsigned bfr[4][2];
#pragma unroll
            for (int nt = 0; nt < 4; nt++) {
                int n = warp_n * 32 + nt * 8 + (lane >> 2);
                bfr[nt][0] = Bs[kf * BS_STRIDE + n];
                bfr[nt][1] = Bs[(kf + 4) * BS_STRIDE + n];
            }
#pragma unroll
            for (int mt = 0; mt < 2; mt++)
#pragma unroll
                for (int nt = 0; nt < 4; nt++)
                    mma_tf32(acc[mt][nt], afr[mt], bfr[nt]);
        }
        __syncthreads();
    }

    // epilogue: add bias, store
#pragma unroll
    for (int nt = 0; nt < 4; nt++) {
        int col = n0 + warp_n * 32 + nt * 8 + (lane & 3) * 2;
        if (col >= GG) continue;
        float ba = b_ih[col] + b_hh[col];
        float bb = b_ih[col + 1] + b_hh[col + 1];
#pragma unroll
        for (int mt = 0; mt < 2; mt++) {
            int row0 = m0 + warp_m * 32 + mt * 16 + (lane >> 2);
            if (row0 < VV) {
                float2 v = make_float2(acc[mt][nt][0] + ba, acc[mt][nt][1] + bb);
                *reinterpret_cast<float2*>(&g_P[row0 * GG + col]) = v;
            }
            int row1 = row0 + 8;
            if (row1 < VV) {
                float2 v = make_float2(acc[mt][nt][2] + ba, acc[mt][nt][3] + bb);
                *reinterpret_cast<float2*>(&g_P[row1 * GG + col]) = v;
            }
        }
    }
}

// ---------------------------------------------------------------------------
// Kernel 2: label_vec[b] = emb[label_word_id[b]] @ ll_W^T + ll_b
// ---------------------------------------------------------------------------
__global__ void label_kernel(const int* __restrict__ label_word_id,
                             const float* __restrict__ emb,
                             const float* __restrict__ ll_W,
                             const float* __restrict__ ll_b) {
    __shared__ float row[EE];
    const int b = blockIdx.x;
    const int w = label_word_id[b];
    for (int e = threadIdx.x; e < EE; e += blockDim.x) row[e] = emb[w * EE + e];
    __syncthreads();
    const int j = threadIdx.x;
    if (j < HH) {
        float s = ll_b[j];
        const float* wr = &ll_W[j * EE];
        for (int e = 0; e < EE; e++) s += row[e] * wr[e];
        g_label[b * HH + j] = s;
    }
}

// ---------------------------------------------------------------------------
// Kernel 3: LSTM recurrence with FFMA2 (fp32x2) gate matvec.
// 128 CTAs x NB=8 batches, 512 threads.
//  - WhhT[g][k] stride 108 (conflict-free LDS.128 of 4 k at once)
//  - hT[k][nb]: batch pairs are one broadcast LDS.64
//  - acc packed across nb pairs -> 4 x fma.rn.f32x2 per (g,k)
//  - P-row gather deferred to loop end (latency hidden under math)
// smem: 43200 + 3200 + 800 + 800 = 48000 floats = 192000 B
// ---------------------------------------------------------------------------
#define WT_STRIDE 108
#define LSTM_SMEM_BYTES (48000 * 4)

__global__ void lstm_kernel(const int* __restrict__ word_id,
                            const int* __restrict__ sen_len,
                            const float* __restrict__ W_hh) {
    extern __shared__ float sm[];
    float* WhhT  = sm;                       // [400][108]
    float* gates = sm + GG * WT_STRIDE;      // [4 pairs][400 g][2]
    float* hT    = gates + 4 * GG * 2;       // [100 k][8 nb]
    float* cS    = hT + HH * NB;             // [8 nb][100 j]
    __shared__ int rows[2][NB];
    __shared__ int senl[NB];

    const int tid = threadIdx.x;
    const int b0 = blockIdx.x * NB;

    for (int idx = tid; idx < GG * HH; idx += 512) {
        int g = idx / HH, k = idx % HH;
        WhhT[g * WT_STRIDE + k] = W_hh[idx];
    }
    for (int idx = tid; idx < NB * HH; idx += 512) {
        hT[idx] = 0.f;
        cS[idx] = 0.f;
    }
    if (tid < NB) {
        senl[tid] = sen_len[b0 + tid];
        rows[0][tid] = word_id[(b0 + tid) * TT + 0];
    }
    __syncthreads();

    const int g = tid;

    for (int t = 0; t < TT; t++) {
        const int buf = t & 1;

        if (g < GG) {
            // issue P gathers early; consumed only after the matvec
            float pv[NB];
#pragma unroll
            for (int nb = 0; nb < NB; nb++)
                pv[nb] = g_P[rows[buf][nb] * GG + g];

            ull acc[4];
#pragma unroll
            for (int p = 0; p < 4; p++) acc[p] = 0ULL;

            const float* wrow = &WhhT[g * WT_STRIDE];
#pragma unroll
            for (int k4 = 0; k4 < HH / 4; k4++) {
                float4 w4 = *reinterpret_cast<const float4*>(wrow + k4 * 4);
#pragma unroll
                for (int j = 0; j < 4; j++) {
                    float wj = (j == 0) ? w4.x : (j == 1) ? w4.y : (j == 2) ? w4.z : w4.w;
                    ull w2 = pack2(wj, wj);
                    const ull* hrow = reinterpret_cast<const ull*>(&hT[(k4 * 4 + j) * NB]);
#pragma unroll
                    for (int p = 0; p < 4; p++)
                        acc[p] = ffma2(w2, hrow[p], acc[p]);
                }
            }
#pragma unroll
            for (int p = 0; p < 4; p++) {
                acc[p] = add2(acc[p], pack2(pv[2 * p], pv[2 * p + 1]));
                *reinterpret_cast<ull*>(&gates[(p * GG + g) * 2]) = acc[p];
            }
        }
        __syncthreads();

        // activation + state update
        for (int idx = tid; idx < NB * HH; idx += 512) {
            int nb = idx / HH, j = idx % HH;
            int p = nb >> 1, c = nb & 1;
            float gi = gates[(p * GG + j) * 2 + c];
            float gf = gates[(p * GG + HH + j) * 2 + c];
            float gg = gates[(p * GG + 2 * HH + j) * 2 + c];
            float go = gates[(p * GG + 3 * HH + j) * 2 + c];
            float si = 1.f / (1.f + __expf(-gi));
            float sf = 1.f / (1.f + __expf(-gf));
            float so = 1.f / (1.f + __expf(-go));
            float sg = fast_tanh(gg);
            float cv = sf * cS[idx] + si * sg;
            float h = so * fast_tanh(cv);
            cS[idx] = cv;
            hT[j * NB + nb] = h;
            int b = b0 + nb;
            g_out[(b * TT + t) * HH + j] = h;
            if (t == senl[nb] - 1) g_last[b * HH + j] = h;
        }
        if (tid < NB && t + 1 < TT)
            rows[1 - buf][tid] = word_id[(b0 + tid) * TT + t + 1];
        __syncthreads();
    }
}

// ---------------------------------------------------------------------------
// Kernel 4: per-batch epilogue: scores, top-4, pos, per_neg, out_f, l_rep, q.
// ---------------------------------------------------------------------------
__global__ void catch_kernel(const int* __restrict__ sen_len,
                             const float* __restrict__ lin_W,
                             const float* __restrict__ lin_b,
                             float* __restrict__ dout) {
    __shared__ float label_s[HH];
    __shared__ float last_s[HH];
    __shared__ float scores[TT];
    __shared__ float red_v[TT];
    __shared__ int   red_i[TT];
    __shared__ float topv[4];
    __shared__ int   topi[4];
    __shared__ float pos_s[HH];
    __shared__ float pneg_s[HH];

    const int b = blockIdx.x;
    const int tid = threadIdx.x;
    const int L = sen_len[b];

    if (tid < HH) {
        label_s[tid] = g_label[b * HH + tid];
        last_s[tid]  = g_last[b * HH + tid];
    }
    __syncthreads();

    {
        float s;
        if (tid < L) {
            s = 0.f;
            const float* o = &g_out[(b * TT + tid) * HH];
            for (int j = 0; j < HH; j++) s += o[j] * label_s[j];
        } else {
            s = -1e30f;
        }
        scores[tid] = s;
    }
    __syncthreads();

    for (int k = 0; k < 4; k++) {
        red_v[tid] = scores[tid];
        red_i[tid] = tid;
        __syncthreads();
        for (int off = TT / 2; off > 0; off >>= 1) {
            if (tid < off) {
                float v2 = red_v[tid + off];
                int   i2 = red_i[tid + off];
                if (v2 > red_v[tid] || (v2 == red_v[tid] && i2 < red_i[tid])) {
                    red_v[tid] = v2;
                    red_i[tid] = i2;
                }
            }
            __syncthreads();
        }
        if (tid == 0) {
            topv[k] = red_v[0];
            topi[k] = red_i[0];
            scores[red_i[0]] = -1e30f;
        }
        __syncthreads();
    }

    if (tid < HH) {
        float p = 0.f;
#pragma unroll
        for (int k = 0; k < 4; k++)
            p += g_out[(b * TT + topi[k]) * HH + tid] * topv[k];
        pos_s[tid] = p;

        float s = 0.f;
        int i0 = topi[0], i1 = topi[1], i2 = topi[2], i3 = topi[3];
        for (int t = 0; t < L; t++) {
            if (t == i0 || t == i1 || t == i2 || t == i3) continue;
            s += g_out[(b * TT + t) * HH + tid];
        }
        pneg_s[tid] = s;
    }
    __syncthreads();

    if (tid < 6) {
        float bo = lin_b[tid];
        float o = bo, l = bo, q = 0.f;
        const float* w = &lin_W[tid * HH];
        for (int j = 0; j < HH; j++) {
            float wj = w[j];
            o += last_s[j] * wj;
            l += pos_s[j] * wj;
            q += pneg_s[j] * wj;
        }
        dout[b * 6 + tid] = o;
        dout[BB * 6 + b * 6 + tid] = l;
        g_q[b * 6 + tid] = q;
    }
}

// ---------------------------------------------------------------------------
// Kernel 5: r_rep = cumsum over batch of q + lin_b. Warp-parallel scan:
// warp r owns row r, 32-chunks with shfl inclusive scan.
// ---------------------------------------------------------------------------
__global__ void scan_kernel(const float* __restrict__ lin_b,
                            float* __restrict__ dout) {
    const int w = threadIdx.x >> 5;
    const int l = threadIdx.x & 31;
    if (w >= 6) return;
    float run = lin_b[w];
    for (int c0 = 0; c0 < BB; c0 += 32) {
        float v = g_q[(c0 + l) * 6 + w];
#pragma unroll
        for (int off = 1; off < 32; off <<= 1) {
            float u = __shfl_up_sync(0xffffffff, v, off);
            if (l >= off) v += u;
        }
        dout[2 * BB * 6 + (c0 + l) * 6 + w] = run + v;
        run += __shfl_sync(0xffffffff, v, 31);
    }
}

// ---------------------------------------------------------------------------
extern "C" void kernel_launch(void* const* d_in, const int* in_sizes, int n_in,
                              void* d_out, int out_size) {
    const int*   word_id       = (const int*)d_in[0];
    const int*   sen_len       = (const int*)d_in[1];
    const int*   label_word_id = (const int*)d_in[2];
    const float* emb           = (const float*)d_in[3];
    const float* W_ih          = (const float*)d_in[4];
    const float* W_hh          = (const float*)d_in[5];
    const float* b_ih          = (const float*)d_in[6];
    const float* b_hh          = (const float*)d_in[7];
    const float* lin_W         = (const float*)d_in[8];
    const float* lin_b         = (const float*)d_in[9];
    const float* ll_W          = (const float*)d_in[10];
    const float* ll_b          = (const float*)d_in[11];
    float* out = (float*)d_out;

    cudaFuncSetAttribute(lstm_kernel,
                         cudaFuncAttributeMaxDynamicSharedMemorySize,
                         LSTM_SMEM_BYTES);

    dim3 ggrid((VV + 127) / 128, (GG + 63) / 64);
    gemm_P_kernel<<<ggrid, 256>>>(emb, W_ih, b_ih, b_hh);
    label_kernel<<<BB, 128>>>(label_word_id, emb, ll_W, ll_b);
    lstm_kernel<<<BB / NB, 512, LSTM_SMEM_BYTES>>>(word_id, sen_len, W_hh);
    catch_kernel<<<BB, 128>>>(sen_len, lin_W, lin_b, out);
    scan_kernel<<<1, 192>>>(lin_b, out);
}

// round 3
// speedup vs baseline: 2.4381x; 1.5502x over previous
#include <cuda_runtime.h>
#include <cuda_bf16.h>
#include <math.h>

// Problem dims
#define BB 1024
#define TT 128
#define EE 300
#define HH 100
#define GG 400     // 4*H
#define VV 50000
#define NB 8       // batches per LSTM CTA
#define NTILES 50  // GG/8
#define KTILES 13  // ceil(HH/8)

typedef unsigned long long ull;

// Scratch (device globals -- no allocation allowed)
__device__ float g_P[VV * GG];        // projected vocab table: emb @ W_ih^T + b  (80 MB)
__device__ float g_out[BB * TT * HH]; // all hidden states (52 MB)
__device__ float g_last[BB * HH];
__device__ float g_label[BB * HH];
__device__ float g_q[BB * 6];         // per_neg @ lin_W^T (pre-cumsum)
__device__ float g_probe;

// ---------------- PTX helpers ----------------
__device__ __forceinline__ unsigned f2tf32(float x) {
    unsigned u;
    asm("cvt.rna.tf32.f32 %0, %1;" : "=r"(u) : "f"(x));
    return u;
}

__device__ __forceinline__ void mma_tf32(float* d, const unsigned* a, const unsigned* b) {
    asm volatile(
        "mma.sync.aligned.m16n8k8.row.col.f32.tf32.tf32.f32 "
        "{%0,%1,%2,%3}, {%4,%5,%6,%7}, {%8,%9}, {%0,%1,%2,%3};"
        : "+f"(d[0]), "+f"(d[1]), "+f"(d[2]), "+f"(d[3])
        : "r"(a[0]), "r"(a[1]), "r"(a[2]), "r"(a[3]), "r"(b[0]), "r"(b[1]));
}

// A-frag rows 8..15 are the zero-padded batches -> a1,a3 are constant 0.
__device__ __forceinline__ void mma_tf32_half(float* d, unsigned a0, unsigned a2,
                                              unsigned b0, unsigned b1) {
    asm volatile(
        "mma.sync.aligned.m16n8k8.row.col.f32.tf32.tf32.f32 "
        "{%0,%1,%2,%3}, {%4,%5,%6,%7}, {%8,%9}, {%0,%1,%2,%3};"
        : "+f"(d[0]), "+f"(d[1]), "+f"(d[2]), "+f"(d[3])
        : "r"(a0), "r"(0u), "r"(a2), "r"(0u), "r"(b0), "r"(b1));
}

__device__ __forceinline__ float fast_tanh(float x) {
    float ax = fabsf(x);
    float e = __expf(-2.f * ax);
    float r = (1.f - e) / (1.f + e);
    return copysignf(r, x);
}

// ---------------------------------------------------------------------------
// Kernel 1: P[v,g] = sum_e emb[v,e]*W_ih[g,e] + b_ih[g] + b_hh[g]
// tf32 tensor-core GEMM. CTA tile 128x64, BK=16, 8 warps (4m x 2n).
// grid = (n_blocks, m_blocks) so the 7 n-blocks sharing an A slab co-run -> L2 reuse.
// ---------------------------------------------------------------------------
#define AS_STRIDE 132
#define BS_STRIDE 68

__global__ void gemm_P_kernel(const float* __restrict__ emb,
                              const float* __restrict__ W_ih,
                              const float* __restrict__ b_ih,
                              const float* __restrict__ b_hh) {
    __shared__ unsigned As[16 * AS_STRIDE];   // [k][m] tf32 bits
    __shared__ unsigned Bs[16 * BS_STRIDE];   // [k][n] tf32 bits

    const int m0 = blockIdx.y * 128;
    const int n0 = blockIdx.x * 64;
    const int tid = threadIdx.x;
    const int lane = tid & 31;
    const int wid = tid >> 5;
    const int warp_m = wid & 3;    // 0..3
    const int warp_n = wid >> 2;   // 0..1

    float acc[2][4][4];
#pragma unroll
    for (int mt = 0; mt < 2; mt++)
#pragma unroll
        for (int nt = 0; nt < 4; nt++)
#pragma unroll
            for (int c = 0; c < 4; c++) acc[mt][nt][c] = 0.f;

    for (int k0 = 0; k0 < EE; k0 += 16) {
#pragma unroll
        for (int i = 0; i < 2; i++) {
            int idx = tid + i * 256;
            int q = idx & 3;
            int m = idx >> 2;
            int gm = m0 + m;
            int gk = k0 + q * 4;
            float4 v = make_float4(0.f, 0.f, 0.f, 0.f);
            if (gm < VV && gk < EE)
                v = *reinterpret_cast<const float4*>(&emb[gm * EE + gk]);
            As[(q * 4 + 0) * AS_STRIDE + m] = f2tf32(v.x);
            As[(q * 4 + 1) * AS_STRIDE + m] = f2tf32(v.y);
            As[(q * 4 + 2) * AS_STRIDE + m] = f2tf32(v.z);
            As[(q * 4 + 3) * AS_STRIDE + m] = f2tf32(v.w);
        }
        {
            int q = tid & 3;
            int n = tid >> 2;
            int gn = n0 + n;
            int gk = k0 + q * 4;
            float4 v = make_float4(0.f, 0.f, 0.f, 0.f);
            if (gn < GG && gk < EE)
                v = *reinterpret_cast<const float4*>(&W_ih[gn * EE + gk]);
            Bs[(q * 4 + 0) * BS_STRIDE + n] = f2tf32(v.x);
            Bs[(q * 4 + 1) * BS_STRIDE + n] = f2tf32(v.y);
            Bs[(q * 4 + 2) * BS_STRIDE + n] = f2tf32(v.z);
            Bs[(q * 4 + 3) * BS_STRIDE + n] = f2tf32(v.w);
        }
        __syncthreads();

#pragma unroll
        for (int kk = 0; kk < 2; kk++) {
            const int kf = kk * 8 + (lane & 3);
            unsigned afr[2][4];
#pragma unroll
            for (int mt = 0; mt < 2; mt++) {
                int m = warp_m * 32 + mt * 16 + (lane >> 2);
                afr[mt][0] = As[kf * AS_STRIDE + m];
                afr[mt][1] = As[kf * AS_STRIDE + m + 8];
                afr[mt][2] = As[(kf + 4) * AS_STRIDE + m];
                afr[mt][3] = As[(kf + 4) * AS_STRIDE + m + 8];
            }
            unsigned bfr[4][2];
#pragma unroll
            for (int nt = 0; nt < 4; nt++) {
                int n = warp_n * 32 + nt * 8 + (lane >> 2);
                bfr[nt][0] = Bs[kf * BS_STRIDE + n];
                bfr[nt][1] = Bs[(kf + 4) * BS_STRIDE + n];
            }
#pragma unroll
            for (int mt = 0; mt < 2; mt++)
#pragma unroll
                for (int nt = 0; nt < 4; nt++)
                    mma_tf32(acc[mt][nt], afr[mt], bfr[nt]);
        }
        __syncthreads();
    }

#pragma unroll
    for (int nt = 0; nt < 4; nt++) {
        int col = n0 + warp_n * 32 + nt * 8 + (lane & 3) * 2;
        if (col >= GG) continue;
        float ba = b_ih[col] + b_hh[col];
        float bb = b_ih[col + 1] + b_hh[col + 1];
#pragma unroll
        for (int mt = 0; mt < 2; mt++) {
            int row0 = m0 + warp_m * 32 + mt * 16 + (lane >> 2);
            if (row0 < VV) {
                float2 v = make_float2(acc[mt][nt][0] + ba, acc[mt][nt][1] + bb);
                *reinterpret_cast<float2*>(&g_P[row0 * GG + col]) = v;
            }
            int row1 = row0 + 8;
            if (row1 < VV) {
                float2 v = make_float2(acc[mt][nt][2] + ba, acc[mt][nt][3] + bb);
                *reinterpret_cast<float2*>(&g_P[row1 * GG + col]) = v;
            }
        }
    }
}

// ---------------------------------------------------------------------------
// Kernel 2: label_vec[b] = emb[label_word_id[b]] @ ll_W^T + ll_b
// ---------------------------------------------------------------------------
__global__ void label_kernel(const int* __restrict__ label_word_id,
                             const float* __restrict__ emb,
                             const float* __restrict__ ll_W,
                             const float* __restrict__ ll_b) {
    __shared__ float row[EE];
    const int b = blockIdx.x;
    const int w = label_word_id[b];
    for (int e = threadIdx.x; e < EE; e += blockDim.x) row[e] = emb[w * EE + e];
    __syncthreads();
    const int j = threadIdx.x;
    if (j < HH) {
        float s = ll_b[j];
        const float* wr = &ll_W[j * EE];
        for (int e = 0; e < EE; e++) s += row[e] * wr[e];
        g_label[b * HH + j] = s;
    }
}

// ---------------------------------------------------------------------------
// Probe: no-op, placed so ncu's fixed capture slot lands on lstm_kernel.
// ---------------------------------------------------------------------------
__global__ void probe_kernel() {
    if (threadIdx.x == 0) g_probe = 0.f;
}

// ---------------------------------------------------------------------------
// Kernel 3: LSTM recurrence on tensor cores (tf32 mma.m16n8k8).
// 128 CTAs x NB=8 batches, 512 threads (16 warps).
// Per step: gates(8x400) = h(8x100 pad->16x104) @ WhhT  via mma;
//   - B (W_hh) pre-converted ONCE into fragment layout in smem (LDS.64/mma)
//   - A (h) written by activation phase directly in fragment layout
//   - batches 8..15 are zero rows -> a1,a3 fragments constant 0
//   - P-row gather overlapped with the mma chain
// smem: Bfrag 50*13*64 u32 + hfrag 13*64 u32 + gates 3200 f = 182528 B
// ---------------------------------------------------------------------------
#define LSTM_SMEM_BYTES ((NTILES * KTILES * 64 + KTILES * 64 + NB * GG) * 4)

__global__ void __launch_bounds__(512, 1)
lstm_kernel(const int* __restrict__ word_id,
            const int* __restrict__ sen_len,
            const float* __restrict__ W_hh) {
    extern __shared__ float sm[];
    unsigned* Bf = reinterpret_cast<unsigned*>(sm);                  // [50][13][32][2]
    unsigned* Hf = reinterpret_cast<unsigned*>(sm) + NTILES * KTILES * 64; // [13][32][2]
    float* gates = sm + NTILES * KTILES * 64 + KTILES * 64;          // [8][400]
    __shared__ int rows[2][NB];
    __shared__ int senl[NB];

    const int tid = threadIdx.x;
    const int b0 = blockIdx.x * NB;
    const int lane = tid & 31;
    const int w = tid >> 5;

    // ---- one-time: W_hh -> B fragments (tf32) ----
    for (int idx = tid; idx < NTILES * KTILES * 64; idx += 512) {
        int v = idx & 1;
        int l = (idx >> 1) & 31;
        int kt = (idx >> 6) % KTILES;
        int nt = idx / (KTILES * 64);
        int n = nt * 8 + (l >> 2);
        int k = kt * 8 + (l & 3) + 4 * v;
        float val = (k < HH) ? W_hh[n * HH + k] : 0.f;
        Bf[idx] = f2tf32(val);
    }
    for (int idx = tid; idx < KTILES * 64; idx += 512) Hf[idx] = 0u;
    if (tid < NB) {
        senl[tid] = sen_len[b0 + tid];
        rows[0][tid] = word_id[(b0 + tid) * TT];
    }

    // activation-thread state (tid < 400): handles (2p, 2p+1) x column aj
    const int aj = tid % 100;
    const int ap = tid / 100;
    const int anb0 = 2 * ap, anb1 = 2 * ap + 1;
    float c0 = 0.f, c1 = 0.f;

    // warp n-tile assignment: w, w+16, w+32 (+48+w for w<2)
    const int ntc = (w < 2) ? 4 : 3;
    int nts[4];
    nts[0] = w; nts[1] = w + 16; nts[2] = w + 32; nts[3] = 48 + w;

    const int nb = lane >> 2;
    const int cl2 = 2 * (lane & 3);

    __syncthreads();

    for (int t = 0; t < TT; t++) {
        const int buf = t & 1;

        // --- phase 1: gates = h @ WhhT + P[word] ---
        float2 pv[4];
        {
            const float* Prow = &g_P[(long)rows[buf][nb] * GG];
#pragma unroll
            for (int i = 0; i < 4; i++)
                if (i < ntc) pv[i] = *reinterpret_cast<const float2*>(&Prow[nts[i] * 8 + cl2]);
        }
        unsigned a0[KTILES], a1[KTILES];
#pragma unroll
        for (int kt = 0; kt < KTILES; kt++) {
            uint2 hv = *reinterpret_cast<const uint2*>(&Hf[(kt * 32 + lane) * 2]);
            a0[kt] = hv.x; a1[kt] = hv.y;
        }
        float acc[4][4];
#pragma unroll
        for (int i = 0; i < 4; i++)
#pragma unroll
            for (int c = 0; c < 4; c++) acc[i][c] = 0.f;

#pragma unroll
        for (int kt = 0; kt < KTILES; kt++) {
#pragma unroll
            for (int i = 0; i < 4; i++) {
                if (i < ntc) {
                    uint2 bv = *reinterpret_cast<const uint2*>(
                        &Bf[((nts[i] * KTILES + kt) * 32 + lane) * 2]);
                    mma_tf32_half(acc[i], a0[kt], a1[kt], bv.x, bv.y);
                }
            }
        }
#pragma unroll
        for (int i = 0; i < 4; i++) {
            if (i < ntc) {
                float2 g2 = make_float2(acc[i][0] + pv[i].x, acc[i][1] + pv[i].y);
                *reinterpret_cast<float2*>(&gates[nb * GG + nts[i] * 8 + cl2]) = g2;
            }
        }
        __syncthreads();

        // --- phase 2: activations + state update + write h fragments ---
        if (tid < 400) {
            const int kt = aj >> 3;
            const int slot = (aj >> 2) & 1;
            {
                float gi = gates[anb0 * GG + aj];
                float gf = gates[anb0 * GG + HH + aj];
                float gg = gates[anb0 * GG + 2 * HH + aj];
                float go = gates[anb0 * GG + 3 * HH + aj];
                float si = 1.f / (1.f + __expf(-gi));
                float sf = 1.f / (1.f + __expf(-gf));
                float so = 1.f / (1.f + __expf(-go));
                float sg = fast_tanh(gg);
                c0 = sf * c0 + si * sg;
                float h = so * fast_tanh(c0);
                Hf[(kt * 32 + ((anb0 << 2) | (aj & 3))) * 2 + slot] = f2tf32(h);
                g_out[((b0 + anb0) * TT + t) * HH + aj] = h;
                if (t == senl[anb0] - 1) g_last[(b0 + anb0) * HH + aj] = h;
            }
            {
                float gi = gates[anb1 * GG + aj];
                float gf = gates[anb1 * GG + HH + aj];
                float gg = gates[anb1 * GG + 2 * HH + aj];
                float go = gates[anb1 * GG + 3 * HH + aj];
                float si = 1.f / (1.f + __expf(-gi));
                float sf = 1.f / (1.f + __expf(-gf));
                float so = 1.f / (1.f + __expf(-go));
                float sg = fast_tanh(gg);
                c1 = sf * c1 + si * sg;
                float h = so * fast_tanh(c1);
                Hf[(kt * 32 + ((anb1 << 2) | (aj & 3))) * 2 + slot] = f2tf32(h);
                g_out[((b0 + anb1) * TT + t) * HH + aj] = h;
                if (t == senl[anb1] - 1) g_last[(b0 + anb1) * HH + aj] = h;
            }
        }
        if (tid < NB && t + 1 < TT)
            rows[1 - buf][tid] = word_id[(b0 + tid) * TT + t + 1];
        __syncthreads();
    }
}

// ---------------------------------------------------------------------------
// Kernel 4: per-batch epilogue: scores, top-4, pos, per_neg, out_f, l_rep, q.
// ---------------------------------------------------------------------------
__global__ void catch_kernel(const int* __restrict__ sen_len,
                             const float* __restrict__ lin_W,
                             const float* __restrict__ lin_b,
                             float* __restrict__ dout) {
    __shared__ float label_s[HH];
    __shared__ float last_s[HH];
    __shared__ float scores[TT];
    __shared__ float red_v[TT];
    __shared__ int   red_i[TT];
    __shared__ float topv[4];
    __shared__ int   topi[4];
    __shared__ float pos_s[HH];
    __shared__ float pneg_s[HH];

    const int b = blockIdx.x;
    const int tid = threadIdx.x;
    const int L = sen_len[b];

    if (tid < HH) {
        label_s[tid] = g_label[b * HH + tid];
        last_s[tid]  = g_last[b * HH + tid];
    }
    __syncthreads();

    {
        float s;
        if (tid < L) {
            s = 0.f;
            const float* o = &g_out[(b * TT + tid) * HH];
            for (int j = 0; j < HH; j++) s += o[j] * label_s[j];
        } else {
            s = -1e30f;
        }
        scores[tid] = s;
    }
    __syncthreads();

    for (int k = 0; k < 4; k++) {
        red_v[tid] = scores[tid];
        red_i[tid] = tid;
        __syncthreads();
        for (int off = TT / 2; off > 0; off >>= 1) {
            if (tid < off) {
                float v2 = red_v[tid + off];
                int   i2 = red_i[tid + off];
                if (v2 > red_v[tid] || (v2 == red_v[tid] && i2 < red_i[tid])) {
                    red_v[tid] = v2;
                    red_i[tid] = i2;
                }
            }
            __syncthreads();
        }
        if (tid == 0) {
            topv[k] = red_v[0];
            topi[k] = red_i[0];
            scores[red_i[0]] = -1e30f;
        }
        __syncthreads();
    }

    if (tid < HH) {
        float p = 0.f;
#pragma unroll
        for (int k = 0; k < 4; k++)
            p += g_out[(b * TT + topi[k]) * HH + tid] * topv[k];
        pos_s[tid] = p;

        float s = 0.f;
        int i0 = topi[0], i1 = topi[1], i2 = topi[2], i3 = topi[3];
        for (int t = 0; t < L; t++) {
            if (t == i0 || t == i1 || t == i2 || t == i3) continue;
            s += g_out[(b * TT + t) * HH + tid];
        }
        pneg_s[tid] = s;
    }
    __syncthreads();

    if (tid < 6) {
        float bo = lin_b[tid];
        float o = bo, l = bo, q = 0.f;
        const float* w = &lin_W[tid * HH];
        for (int j = 0; j < HH; j++) {
            float wj = w[j];
            o += last_s[j] * wj;
            l += pos_s[j] * wj;
            q += pneg_s[j] * wj;
        }
        dout[b * 6 + tid] = o;
        dout[BB * 6 + b * 6 + tid] = l;
        g_q[b * 6 + tid] = q;
    }
}

// ---------------------------------------------------------------------------
// Kernel 5: r_rep = cumsum over batch of q + lin_b (warp-parallel scan).
// ---------------------------------------------------------------------------
__global__ void scan_kernel(const float* __restrict__ lin_b,
                            float* __restrict__ dout) {
    const int w = threadIdx.x >> 5;
    const int l = threadIdx.x & 31;
    if (w >= 6) return;
    float run = lin_b[w];
    for (int c0 = 0; c0 < BB; c0 += 32) {
        float v = g_q[(c0 + l) * 6 + w];
#pragma unroll
        for (int off = 1; off < 32; off <<= 1) {
            float u = __shfl_up_sync(0xffffffff, v, off);
            if (l >= off) v += u;
        }
        dout[2 * BB * 6 + (c0 + l) * 6 + w] = run + v;
        run += __shfl_sync(0xffffffff, v, 31);
    }
}

// ---------------------------------------------------------------------------
extern "C" void kernel_launch(void* const* d_in, const int* in_sizes, int n_in,
                              void* d_out, int out_size) {
    const int*   word_id       = (const int*)d_in[0];
    const int*   sen_len       = (const int*)d_in[1];
    const int*   label_word_id = (const int*)d_in[2];
    const float* emb           = (const float*)d_in[3];
    const float* W_ih          = (const float*)d_in[4];
    const float* W_hh          = (const float*)d_in[5];
    const float* b_ih          = (const float*)d_in[6];
    const float* b_hh          = (const float*)d_in[7];
    const float* lin_W         = (const float*)d_in[8];
    const float* lin_b         = (const float*)d_in[9];
    const float* ll_W          = (const float*)d_in[10];
    const float* ll_b          = (const float*)d_in[11];
    float* out = (float*)d_out;

    cudaFuncSetAttribute(lstm_kernel,
                         cudaFuncAttributeMaxDynamicSharedMemorySize,
                         LSTM_SMEM_BYTES);

    dim3 ggrid((GG + 63) / 64, (VV + 127) / 128);   // n fastest -> A slab L2 reuse
    gemm_P_kernel<<<ggrid, 256>>>(emb, W_ih, b_ih, b_hh);            // idx 0
    label_kernel<<<BB, 128>>>(label_word_id, emb, ll_W, ll_b);       // idx 1
    probe_kernel<<<1, 32>>>();                                       // idx 2 (shifts ncu slot)
    lstm_kernel<<<BB / NB, 512, LSTM_SMEM_BYTES>>>(word_id, sen_len, W_hh); // idx 3
    catch_kernel<<<BB, 128>>>(sen_len, lin_W, lin_b, out);           // idx 4
    scan_kernel<<<1, 192>>>(lin_b, out);                             // idx 5
}